// round 1
// baseline (speedup 1.0000x reference)
#include <cuda_runtime.h>
#include <math.h>

#define B_   128
#define P_   2048
#define NB_  2000
#define NF_  250
#define NC_  16
#define R_   128
#define LS_  1750      // NB - NF
#define FT_  1751      // NB - NF + 1

// ---------------- scratch (static device globals; no allocations) ----------------
__device__ float d_filt[FT_];
__device__ float d_stimdot[B_];
__device__ float d_gensig[B_ * LS_];

// ---------------- K1: filt_time[t] = sum_i stim_time[t+i] * stf[i] ----------------
__global__ void k_filt(const float* __restrict__ stim_time,
                       const float* __restrict__ stf) {
    int t = blockIdx.x * blockDim.x + threadIdx.x;
    if (t >= FT_) return;
    double a = 0.0;
    #pragma unroll 10
    for (int i = 0; i < NF_; ++i)
        a += (double)stim_time[t + i] * (double)stf[i];
    d_filt[t] = (float)a;
}

// ---------------- K2: stim_dot[b] = sum_p spat[b,p] * sf[p] ----------------
__global__ void k_stimdot(const float* __restrict__ spat,
                          const float* __restrict__ sf) {
    int b = blockIdx.x * blockDim.x + threadIdx.x;
    if (b >= B_) return;
    const float* row = spat + (size_t)b * P_;
    double a = 0.0;
    for (int p = 0; p < P_; ++p)
        a += (double)row[p] * (double)sf[p];
    d_stimdot[b] = (float)a;
}

// ---------------- K3: gensig[b,t] = (stim_dot[b]*filt[t] + bias) + coup[b,t] ----------------
// coup via exact selection: coupling cells are {0,1}, so coup = sum of selected
// filter coefficients; accumulate in double (two chains to break latency).
__global__ void k_gensig(const float* __restrict__ cc,
                         const float* __restrict__ cK,
                         const float* __restrict__ bias) {
    __shared__ float sK[NC_ * NF_];
    for (int i = threadIdx.x; i < NC_ * NF_; i += blockDim.x) sK[i] = cK[i];
    __syncthreads();

    int t = blockIdx.x * blockDim.x + threadIdx.x;
    int b = blockIdx.y;
    if (t >= LS_) return;

    double acc0 = 0.0, acc1 = 0.0;
    for (int c = 0; c < NC_; ++c) {
        const float* p  = cc + ((size_t)(b * NC_ + c)) * NB_ + t;
        const float* kk = sK + c * NF_;
        #pragma unroll 2
        for (int i = 0; i < NF_; i += 2) {
            float v0 = p[i];
            float v1 = p[i + 1];
            if (v0 != 0.0f) acc0 += (double)kk[i];
            if (v1 != 0.0f) acc1 += (double)kk[i + 1];
        }
    }
    float coup = (float)(acc0 + acc1);
    float sg = __fmul_rn(d_stimdot[b], d_filt[t]);
    sg = __fadd_rn(sg, bias[0]);
    d_gensig[b * LS_ + t] = __fadd_rn(sg, coup);
}

// ---------------- K4: the sequential Bernoulli-GLM simulation ----------------
// One warp = 2 sequences (same b, r and r+1). 16 lanes per sequence.
// Lane q (0..15) of each half holds window positions k = 16q+i (i=0..15) as
// 0/1 floats in registers, with phase rotation: pos 16q+i lives in w[(i+t)&15].
// Per step: 16 FFMA dot + 4-level shfl.xor reduce + 1 shfl boundary shift +
// sigmoid + compare. New spike inserted at position 249 (q==15, i==9).
__global__ void __launch_bounds__(256)
k_sim(const float* __restrict__ init,
      const float* __restrict__ ff,
      const float* __restrict__ u,
      float* __restrict__ out) {
    const unsigned FULL = 0xffffffffu;
    const int lane = threadIdx.x & 31;
    const int gw   = (blockIdx.x * blockDim.x + threadIdx.x) >> 5;  // 0..8191
    const int b    = gw >> 6;        // 128 b's
    const int rp   = gw & 63;        // 64 r-pairs per b
    const int half = lane >> 4;      // which sequence in the warp
    const int q    = lane & 15;      // lane within the 16-lane group
    const int r    = rp * 2 + half;
    const int seq  = b * R_ + r;

    // window + filter taps in registers
    float f[16], w[16];
    #pragma unroll
    for (int i = 0; i < 16; ++i) {
        int k = q * 16 + i;
        bool valid = (k < NF_);
        f[i] = valid ? ff[k] : 0.0f;
        w[i] = valid ? init[b * NF_ + k] : 0.0f;
    }

    // write the initial window section to the output rows
    float* orow = out + (size_t)seq * NB_;
    for (int k = q; k < NF_; k += 16)
        orow[k] = init[b * NF_ + k];

    const float* gens = d_gensig + b * LS_;
    const int src_shift = (lane & 16) | ((lane + 1) & 15);  // next lane within group
    const int src_u     = lane & 16;
    float outv = 0.0f;

    for (int t0 = 0; t0 < LS_; t0 += 16) {
        const int tq = t0 + q;
        float uval = 0.0f, gval = 0.0f;
        if (tq < LS_) {
            uval = u[(size_t)tq * (B_ * R_) + seq];   // u[t][b][r]
            gval = gens[tq];
        }
        int nsteps = LS_ - t0; if (nsteps > 16) nsteps = 16;

        #pragma unroll
        for (int s = 0; s < 16; ++s) {
            if (s >= nsteps) break;
            // feedback dot: taps k = 16q+i, phase-rotated registers
            float acc = w[s & 15] * f[0];
            #pragma unroll
            for (int i = 1; i < 16; ++i)
                acc = fmaf(w[(i + s) & 15], f[i], acc);
            // reduce across the 16-lane group
            acc += __shfl_xor_sync(FULL, acc, 1);
            acc += __shfl_xor_sync(FULL, acc, 2);
            acc += __shfl_xor_sync(FULL, acc, 4);
            acc += __shfl_xor_sync(FULL, acc, 8);

            float gt = __shfl_sync(FULL, gval, s);          // gensig[b][t], same both halves
            float ut = __shfl_sync(FULL, uval, src_u | s);  // this half's u[t]

            float g = gt + acc;
            float e = expf(-g);                 // libdevice __nv_expf (matches XLA exp)
            float sig = 1.0f / (1.0f + e);      // IEEE-rounded f32 division
            float spike = (ut < sig) ? 1.0f : 0.0f;

            if (q == s) outv = spike;           // lane s keeps spike for step t0+s

            // shift: pos 16q+15 <- neighbor group-lane's pos 16(q+1)+0
            float inc = __shfl_sync(FULL, w[s & 15], src_shift);
            w[s & 15] = inc;
            // insert new spike at position 249 (q==15, i==9) for phase t+1
            if (q == 15) w[(s + 10) & 15] = spike;
        }

        if (tq < LS_) orow[NF_ + tq] = outv;
    }
}

// ---------------- launch ----------------
extern "C" void kernel_launch(void* const* d_in, const int* in_sizes, int n_in,
                              void* d_out, int out_size) {
    (void)in_sizes; (void)n_in; (void)out_size;
    const float* stim_spat = (const float*)d_in[0];
    const float* stim_time = (const float*)d_in[1];
    const float* init      = (const float*)d_in[2];
    const float* cc        = (const float*)d_in[3];
    const float* sf        = (const float*)d_in[4];
    const float* bias      = (const float*)d_in[5];
    const float* stf       = (const float*)d_in[6];
    const float* ff        = (const float*)d_in[7];
    const float* cK        = (const float*)d_in[8];
    const float* u         = (const float*)d_in[9];
    float* out = (float*)d_out;

    k_filt<<<(FT_ + 255) / 256, 256>>>(stim_time, stf);
    k_stimdot<<<1, 128>>>(stim_spat, sf);
    dim3 g3((LS_ + 255) / 256, B_);
    k_gensig<<<g3, 256>>>(cc, cK, bias);

    // 8192 warps (2 sequences each) -> 1024 blocks of 256 threads
    k_sim<<<1024, 256>>>(init, ff, u, out);
}

// round 2
// speedup vs baseline: 3.2755x; 3.2755x over previous
#include <cuda_runtime.h>
#include <math.h>

#define B_   128
#define P_   2048
#define NB_  2000
#define NF_  250
#define NC_  16
#define R_   128
#define LS_  1750      // NB - NF
#define FT_  1751      // NB - NF + 1
#define NW_  63        // words of 32 bits covering NB=2000 (uses 62.5)
#define NWP_ 64        // padded row stride in words

// ---------------- scratch (static device globals; no allocations) ----------------
__device__ float d_filt[FT_];
__device__ float d_stimdot[B_];
__device__ float d_gensig[B_ * LS_];
__device__ unsigned d_bm[B_ * NC_ * NWP_];   // bitmask of cc != 0

// ---------------- K1: filt_time[t] = sum_i stim_time[t+i] * stf[i] ----------------
__global__ void k_filt(const float* __restrict__ stim_time,
                       const float* __restrict__ stf) {
    int t = blockIdx.x * blockDim.x + threadIdx.x;
    if (t >= FT_) return;
    double a = 0.0;
    #pragma unroll 10
    for (int i = 0; i < NF_; ++i)
        a += (double)stim_time[t + i] * (double)stf[i];
    d_filt[t] = (float)a;
}

// ---------------- K2: stim_dot[b] = sum_p spat[b,p] * sf[p] ----------------
__global__ void k_stimdot(const float* __restrict__ spat,
                          const float* __restrict__ sf) {
    int b = blockIdx.x * blockDim.x + threadIdx.x;
    if (b >= B_) return;
    const float* row = spat + (size_t)b * P_;
    double a = 0.0;
    for (int p = 0; p < P_; ++p)
        a += (double)row[p] * (double)sf[p];
    d_stimdot[b] = (float)a;
}

// ---------------- K-pack: bitmask of cc != 0 ----------------
// warp w handles (row = w/63, word = w%63); rows are (b*NC + c).
__global__ void k_pack(const float* __restrict__ cc) {
    int gid  = blockIdx.x * blockDim.x + threadIdx.x;
    int warp = gid >> 5;
    int lane = gid & 31;
    int row  = warp / NW_;
    int word = warp - row * NW_;
    if (row >= B_ * NC_) return;
    int elem = word * 32 + lane;
    float v = (elem < NB_) ? cc[(size_t)row * NB_ + elem] : 0.0f;
    unsigned m = __ballot_sync(0xffffffffu, v != 0.0f);
    if (lane == 0) d_bm[row * NWP_ + word] = m;
}

// ---------------- K3: gensig[b,t] = (stim_dot[b]*filt[t] + bias) + coup[b,t] ----------------
// coup via exact sparse selection: walk set bits of the binary mask, sum the
// corresponding coupling-filter coefficients in double. Only ~200 live adds
// per (b,t) instead of 4000 predicated slots.
__global__ void __launch_bounds__(256)
k_gensig(const float* __restrict__ cK,
         const float* __restrict__ bias) {
    __shared__ double sKd[NC_ * 256];          // taps zero-padded 250 -> 256
    __shared__ unsigned sbm[NC_ * NWP_];

    const int tid = threadIdx.x;
    const int b   = blockIdx.y;

    for (int i = tid; i < NC_ * 256; i += blockDim.x) {
        int c = i >> 8, k = i & 255;
        sKd[i] = (k < NF_) ? (double)cK[c * NF_ + k] : 0.0;
    }
    for (int i = tid; i < NC_ * NWP_; i += blockDim.x)
        sbm[i] = d_bm[b * NC_ * NWP_ + i];
    __syncthreads();

    const int t = blockIdx.x * blockDim.x + tid;
    if (t >= LS_) return;

    const int w0 = t >> 5;
    const int o  = t & 31;

    double acc = 0.0;
    #pragma unroll 1
    for (int c = 0; c < NC_; ++c) {
        const unsigned* bm = sbm + c * NWP_ + w0;
        const double*   kd = sKd + c * 256;
        #pragma unroll
        for (int k = 0; k < 8; ++k) {
            // bits [t+32k, t+32k+32) of the row, aligned to tap index 32k..
            unsigned w = __funnelshift_r(bm[k], bm[k + 1], o);
            while (w) {
                int i = __ffs(w) - 1;
                w &= w - 1;
                acc += kd[(k << 5) + i];   // taps >= 250 hit the 0.0 padding
            }
        }
    }
    float coup = (float)acc;
    float sg = __fmul_rn(d_stimdot[b], d_filt[t]);
    sg = __fadd_rn(sg, bias[0]);
    d_gensig[b * LS_ + t] = __fadd_rn(sg, coup);
}

// ---------------- K4: the sequential Bernoulli-GLM simulation ----------------
// (unchanged from the bit-exact R1 version)
__global__ void __launch_bounds__(256)
k_sim(const float* __restrict__ init,
      const float* __restrict__ ff,
      const float* __restrict__ u,
      float* __restrict__ out) {
    const unsigned FULL = 0xffffffffu;
    const int lane = threadIdx.x & 31;
    const int gw   = (blockIdx.x * blockDim.x + threadIdx.x) >> 5;  // 0..8191
    const int b    = gw >> 6;        // 128 b's
    const int rp   = gw & 63;        // 64 r-pairs per b
    const int half = lane >> 4;      // which sequence in the warp
    const int q    = lane & 15;      // lane within the 16-lane group
    const int r    = rp * 2 + half;
    const int seq  = b * R_ + r;

    float f[16], w[16];
    #pragma unroll
    for (int i = 0; i < 16; ++i) {
        int k = q * 16 + i;
        bool valid = (k < NF_);
        f[i] = valid ? ff[k] : 0.0f;
        w[i] = valid ? init[b * NF_ + k] : 0.0f;
    }

    float* orow = out + (size_t)seq * NB_;
    for (int k = q; k < NF_; k += 16)
        orow[k] = init[b * NF_ + k];

    const float* gens = d_gensig + b * LS_;
    const int src_shift = (lane & 16) | ((lane + 1) & 15);
    const int src_u     = lane & 16;
    float outv = 0.0f;

    for (int t0 = 0; t0 < LS_; t0 += 16) {
        const int tq = t0 + q;
        float uval = 0.0f, gval = 0.0f;
        if (tq < LS_) {
            uval = u[(size_t)tq * (B_ * R_) + seq];   // u[t][b][r]
            gval = gens[tq];
        }
        int nsteps = LS_ - t0; if (nsteps > 16) nsteps = 16;

        #pragma unroll
        for (int s = 0; s < 16; ++s) {
            if (s >= nsteps) break;
            float acc = w[s & 15] * f[0];
            #pragma unroll
            for (int i = 1; i < 16; ++i)
                acc = fmaf(w[(i + s) & 15], f[i], acc);
            acc += __shfl_xor_sync(FULL, acc, 1);
            acc += __shfl_xor_sync(FULL, acc, 2);
            acc += __shfl_xor_sync(FULL, acc, 4);
            acc += __shfl_xor_sync(FULL, acc, 8);

            float gt = __shfl_sync(FULL, gval, s);
            float ut = __shfl_sync(FULL, uval, src_u | s);

            float g = gt + acc;
            float e = expf(-g);
            float sig = 1.0f / (1.0f + e);
            float spike = (ut < sig) ? 1.0f : 0.0f;

            if (q == s) outv = spike;

            float inc = __shfl_sync(FULL, w[s & 15], src_shift);
            w[s & 15] = inc;
            if (q == 15) w[(s + 10) & 15] = spike;
        }

        if (tq < LS_) orow[NF_ + tq] = outv;
    }
}

// ---------------- launch ----------------
extern "C" void kernel_launch(void* const* d_in, const int* in_sizes, int n_in,
                              void* d_out, int out_size) {
    (void)in_sizes; (void)n_in; (void)out_size;
    const float* stim_spat = (const float*)d_in[0];
    const float* stim_time = (const float*)d_in[1];
    const float* init      = (const float*)d_in[2];
    const float* cc        = (const float*)d_in[3];
    const float* sf        = (const float*)d_in[4];
    const float* bias      = (const float*)d_in[5];
    const float* stf       = (const float*)d_in[6];
    const float* ff        = (const float*)d_in[7];
    const float* cK        = (const float*)d_in[8];
    const float* u         = (const float*)d_in[9];
    float* out = (float*)d_out;

    k_filt<<<(FT_ + 255) / 256, 256>>>(stim_time, stf);
    k_stimdot<<<1, 128>>>(stim_spat, sf);

    // pack cc bitmasks: 128*16 rows * 63 words * 32 lanes threads
    int pack_threads = B_ * NC_ * NW_ * 32;
    k_pack<<<(pack_threads + 255) / 256, 256>>>(cc);

    dim3 g3((LS_ + 255) / 256, B_);
    k_gensig<<<g3, 256>>>(cK, bias);

    k_sim<<<1024, 256>>>(init, ff, u, out);
}

// round 3
// speedup vs baseline: 4.7596x; 1.4531x over previous
#include <cuda_runtime.h>
#include <math.h>

#define B_   128
#define P_   2048
#define NB_  2000
#define NF_  250
#define NC_  16
#define R_   128
#define LS_  1750      // NB - NF
#define FT_  1751      // NB - NF + 1
#define NW_  63        // 32-bit words covering NB=2000
#define NWP_ 64        // padded row stride in words

// ---------------- scratch (static device globals; no allocations) ----------------
__device__ float d_filt[FT_];
__device__ float d_stimdot[B_];
__device__ float d_gensig[B_ * LS_];
__device__ unsigned d_bm[B_ * NC_ * NWP_];   // bitmask of cc != 0

// ---------------- K1: filt_time[t] = sum_i stim_time[t+i] * stf[i] ----------------
// one warp per t; double accumulation -> order-free
__global__ void k_filt(const float* __restrict__ stim_time,
                       const float* __restrict__ stf) {
    int warp = (blockIdx.x * blockDim.x + threadIdx.x) >> 5;
    int lane = threadIdx.x & 31;
    if (warp >= FT_) return;
    double a = 0.0;
    #pragma unroll
    for (int i = lane; i < NF_; i += 32)
        a += (double)stim_time[warp + i] * (double)stf[i];
    #pragma unroll
    for (int m = 16; m; m >>= 1) a += __shfl_xor_sync(0xffffffffu, a, m);
    if (lane == 0) d_filt[warp] = (float)a;
}

// ---------------- K2: stim_dot[b] = sum_p spat[b,p] * sf[p] ----------------
// one warp per b; double accumulation -> order-free
__global__ void k_stimdot(const float* __restrict__ spat,
                          const float* __restrict__ sf) {
    int warp = (blockIdx.x * blockDim.x + threadIdx.x) >> 5;
    int lane = threadIdx.x & 31;
    if (warp >= B_) return;
    const float* row = spat + (size_t)warp * P_;
    double a = 0.0;
    for (int p = lane; p < P_; p += 32)
        a += (double)row[p] * (double)sf[p];
    #pragma unroll
    for (int m = 16; m; m >>= 1) a += __shfl_xor_sync(0xffffffffu, a, m);
    if (lane == 0) d_stimdot[warp] = (float)a;
}

// ---------------- K-pack: bitmask of cc != 0 ----------------
__global__ void k_pack(const float* __restrict__ cc) {
    int gid  = blockIdx.x * blockDim.x + threadIdx.x;
    int warp = gid >> 5;
    int lane = gid & 31;
    int row  = warp / NW_;
    int word = warp - row * NW_;
    if (row >= B_ * NC_) return;
    int elem = word * 32 + lane;
    float v = (elem < NB_) ? cc[(size_t)row * NB_ + elem] : 0.0f;
    unsigned m = __ballot_sync(0xffffffffu, v != 0.0f);
    if (lane == 0) d_bm[row * NWP_ + word] = m;
}

// ---------------- K3: gensig[b,t] ----------------
// 4 lanes per t (4 cells each) to cut the serial double-add chain 4x;
// double accumulation makes the cross-lane combine order-free.
__global__ void __launch_bounds__(256)
k_gensig(const float* __restrict__ cK,
         const float* __restrict__ bias) {
    __shared__ double sKd[NC_ * 256];          // taps zero-padded 250 -> 256
    __shared__ unsigned sbm[NC_ * NWP_];

    const int tid = threadIdx.x;
    const int b   = blockIdx.y;

    for (int i = tid; i < NC_ * 256; i += 256) {
        int c = i >> 8, k = i & 255;
        sKd[i] = (k < NF_) ? (double)cK[c * NF_ + k] : 0.0;
    }
    for (int i = tid; i < NC_ * NWP_; i += 256)
        sbm[i] = d_bm[b * NC_ * NWP_ + i];
    __syncthreads();

    const int cg = tid & 3;                    // cell group 0..3
    const int t  = blockIdx.x * 64 + (tid >> 2);

    double acc = 0.0;
    if (t < LS_) {
        const int w0 = t >> 5;
        const int o  = t & 31;
        #pragma unroll 1
        for (int c = cg * 4; c < cg * 4 + 4; ++c) {
            const unsigned* bm = sbm + c * NWP_ + w0;
            const double*   kd = sKd + c * 256;
            #pragma unroll
            for (int k = 0; k < 8; ++k) {
                unsigned wd = __funnelshift_r(bm[k], bm[k + 1], o);
                while (wd) {
                    int i = __ffs(wd) - 1;
                    wd &= wd - 1;
                    acc += kd[(k << 5) + i];
                }
            }
        }
    }
    acc += __shfl_xor_sync(0xffffffffu, acc, 1);
    acc += __shfl_xor_sync(0xffffffffu, acc, 2);

    if (cg == 0 && t < LS_) {
        float coup = (float)acc;
        float sg = __fmul_rn(d_stimdot[b], d_filt[t]);
        sg = __fadd_rn(sg, bias[0]);
        d_gensig[b * LS_ + t] = __fadd_rn(sg, coup);
    }
}

// ---------------- K4: sequential Bernoulli-GLM simulation ----------------
// 4 sequences per warp, 8 lanes each, 32 window positions per lane in
// registers (phase-rotated mod 32). Arithmetic is bit-identical to the
// verified 2-seq version: per lane two 16-deep serial FMA chains A,B
// (= old lanes 2q, 2q+1), A+B = old butterfly level 1 (commutative),
// then shfl_xor 1,2,4 = old levels 2,4,8.
__global__ void __launch_bounds__(128)
k_sim(const float* __restrict__ init,
      const float* __restrict__ ff,
      const float* __restrict__ u,
      float* __restrict__ out) {
    const unsigned FULL = 0xffffffffu;
    const int lane = threadIdx.x & 31;
    const int gw   = (blockIdx.x * blockDim.x + threadIdx.x) >> 5;  // 0..4095
    const int b    = gw >> 5;         // 32 warps per b
    const int rq   = gw & 31;
    const int half = lane >> 3;       // 0..3: sequence within the warp
    const int q    = lane & 7;        // lane within the 8-lane group
    const int seq  = b * R_ + rq * 4 + half;

    float f[32], w[32];
    #pragma unroll
    for (int i = 0; i < 32; ++i) {
        int k = q * 32 + i;
        bool valid = (k < NF_);
        f[i] = valid ? ff[k] : 0.0f;
        w[i] = valid ? init[b * NF_ + k] : 0.0f;
    }

    float* orow = out + (size_t)seq * NB_;
    for (int k = q; k < NF_; k += 8)
        orow[k] = init[b * NF_ + k];

    const float* gens = d_gensig + b * LS_;
    const int src_half  = lane & 24;
    const int src_shift = src_half | ((q + 1) & 7);

    for (int t0 = 0; t0 < LS_; t0 += 32) {
        float gval = (t0 + lane < LS_) ? gens[t0 + lane] : 0.0f;
        float uval[4], outv[4];
        #pragma unroll
        for (int m = 0; m < 4; ++m) {
            int t = t0 + q + 8 * m;
            uval[m] = (t < LS_) ? u[(size_t)t * (B_ * R_) + seq] : 0.0f;
            outv[m] = 0.0f;
        }

        #pragma unroll
        for (int s = 0; s < 32; ++s) {
            // two independent 16-deep chains (exact old per-lane partials)
            float a  = w[s & 31]        * f[0];
            float bb = w[(16 + s) & 31] * f[16];
            #pragma unroll
            for (int i = 1; i < 16; ++i) {
                a  = fmaf(w[(i + s) & 31],      f[i],      a);
                bb = fmaf(w[(16 + i + s) & 31], f[16 + i], bb);
            }
            float acc = a + bb;
            acc += __shfl_xor_sync(FULL, acc, 1);
            acc += __shfl_xor_sync(FULL, acc, 2);
            acc += __shfl_xor_sync(FULL, acc, 4);

            float gt = __shfl_sync(FULL, gval, s);
            float ut = __shfl_sync(FULL, uval[s >> 3], src_half | (s & 7));

            float g = gt + acc;
            float e = expf(-g);
            float sig = 1.0f / (1.0f + e);
            float spike = (ut < sig) ? 1.0f : 0.0f;

            if (q == (s & 7)) outv[s >> 3] = spike;

            // shift: slot s&31 (pos 32q) <- neighbor's pos 32(q+1)
            float inc = __shfl_sync(FULL, w[s & 31], src_shift);
            w[s & 31] = inc;
            // insert new spike at position 249 (q==7, i==25) for phase s+1
            if (q == 7) w[(s + 26) & 31] = spike;
        }

        #pragma unroll
        for (int m = 0; m < 4; ++m) {
            int t = t0 + q + 8 * m;
            if (t < LS_) orow[NF_ + t] = outv[m];
        }
    }
}

// ---------------- launch ----------------
extern "C" void kernel_launch(void* const* d_in, const int* in_sizes, int n_in,
                              void* d_out, int out_size) {
    (void)in_sizes; (void)n_in; (void)out_size;
    const float* stim_spat = (const float*)d_in[0];
    const float* stim_time = (const float*)d_in[1];
    const float* init      = (const float*)d_in[2];
    const float* cc        = (const float*)d_in[3];
    const float* sf        = (const float*)d_in[4];
    const float* bias      = (const float*)d_in[5];
    const float* stf       = (const float*)d_in[6];
    const float* ff        = (const float*)d_in[7];
    const float* cK        = (const float*)d_in[8];
    const float* u         = (const float*)d_in[9];
    float* out = (float*)d_out;

    // 128*16 rows * 63 words, one warp-lane per element
    int pack_threads = B_ * NC_ * NW_ * 32;
    k_pack<<<(pack_threads + 255) / 256, 256>>>(cc);

    k_filt<<<(FT_ * 32 + 255) / 256, 256>>>(stim_time, stf);
    k_stimdot<<<(B_ * 32 + 255) / 256, 256>>>(stim_spat, sf);

    dim3 g3((LS_ + 63) / 64, B_);
    k_gensig<<<g3, 256>>>(cK, bias);

    // 4096 warps (4 sequences each) -> 1024 blocks of 128 threads
    k_sim<<<1024, 128>>>(init, ff, u, out);
}